// round 2
// baseline (speedup 1.0000x reference)
#include <cuda_runtime.h>

#define B   8
#define C   64
#define IC  32
#define HW  65536
#define NV  32768                 // view columns (HW/2)
#define TOT (IC*HW)               // 2097152 elements per batch per tensor

typedef unsigned long long ull;

// ---------------- scratch (device globals; no runtime allocation) ----------------
__device__ float s_phi  [(size_t)B*TOT];   // 64 MiB
__device__ float s_g    [(size_t)B*TOT];   // 64 MiB
__device__ float s_theta[(size_t)B*TOT];   // 64 MiB
__device__ unsigned int s_maxk[2*B];       // encoded float max: [0..7]=phi, [8..15]=g
__device__ float s_att[B*64*64];           // unnormalized att per batch
__device__ float s_sum[2*B];               // [0..7]=Sphi, [8..15]=Sg
__device__ float s_C[B*2*64*64];           // folded (mask*att/(S*S)) matrices

// ---------------- helpers ----------------
__device__ __forceinline__ unsigned int enc_f(float f) {
    unsigned int u = __float_as_uint(f);
    return (u & 0x80000000u) ? ~u : (u | 0x80000000u);
}
__device__ __forceinline__ float dec_f(unsigned int k) {
    return (k & 0x80000000u) ? __uint_as_float(k ^ 0x80000000u) : __uint_as_float(~k);
}
__device__ __forceinline__ ull fma2(ull a, ull b, ull c) {
    ull d;
    asm("fma.rn.f32x2 %0, %1, %2, %3;" : "=l"(d) : "l"(a), "l"(b), "l"(c));
    return d;
}
__device__ __forceinline__ ull pack2(float x) {
    ull r; asm("mov.b64 %0, {%1, %1};" : "=l"(r) : "f"(x)); return r;
}
__device__ __forceinline__ float2 unpack2(ull v) {
    float2 f; asm("mov.b64 {%0, %1}, %2;" : "=f"(f.x), "=f"(f.y) : "l"(v)); return f;
}

// ---------------- K0: reset accumulators ----------------
__global__ void k_init() {
    int i = blockIdx.x * 256 + threadIdx.x;
    if (i < B*4096) s_att[i] = 0.0f;
    if (i < 2*B) { s_sum[i] = 0.0f; s_maxk[i] = 0u; }
}

// ---------------- K1: 3x 1x1 conv (64->32) + per-batch max of phi/g ----------------
// tile: 96 output rows (32 phi | 32 g | 32 theta) x 64 pixels; 256 threads,
// each thread computes 3 rows x 8 px using packed f32x2 FMA.
__global__ __launch_bounds__(256) void k_conv(const float* __restrict__ x,
                                              const float* __restrict__ wp,
                                              const float* __restrict__ wt,
                                              const float* __restrict__ wg) {
    __shared__ float xs[64][64];     // [cin][px] 16 KB
    __shared__ float ws[96][65];     // padded   24.4 KB
    const int tid = threadIdx.x;
    const int b   = blockIdx.x >> 10;          // 1024 blocks per batch
    const int p0  = (blockIdx.x & 1023) << 6;

    for (int i = tid; i < 96*64; i += 256) {
        int r = i >> 6, k = i & 63;
        float v = (r < 32) ? wp[i] : (r < 64 ? wg[i - 2048] : wt[i - 4096]);
        ws[r][k] = v;
    }
    const float* xb = x + ((size_t)b << 22) + p0;
    for (int i = tid; i < 64*64; i += 256) {
        int ch = i >> 6, p = i & 63;
        xs[ch][p] = xb[((size_t)ch << 16) + p];
    }
    __syncthreads();

    const int rg = tid >> 3;          // 0..31 -> rows rg*3 .. rg*3+2
    const int pg = tid & 7;           // 0..7  -> px  pg*8 .. pg*8+7
    const int r0 = rg * 3;
    const int c0 = pg * 8;

    ull acc[3][4];
    #pragma unroll
    for (int i = 0; i < 3; i++)
        #pragma unroll
        for (int j = 0; j < 4; j++) acc[i][j] = 0ull;

    #pragma unroll 4
    for (int k = 0; k < 64; k++) {
        ulonglong2 xa = *(const ulonglong2*)&xs[k][c0];
        ulonglong2 xc = *(const ulonglong2*)&xs[k][c0 + 4];
        #pragma unroll
        for (int i = 0; i < 3; i++) {
            ull w2 = pack2(ws[r0 + i][k]);
            acc[i][0] = fma2(w2, xa.x, acc[i][0]);
            acc[i][1] = fma2(w2, xa.y, acc[i][1]);
            acc[i][2] = fma2(w2, xc.x, acc[i][2]);
            acc[i][3] = fma2(w2, xc.y, acc[i][3]);
        }
    }

    float mphi = -1e30f, mg = -1e30f;
    #pragma unroll
    for (int i = 0; i < 3; i++) {
        int r  = r0 + i;
        int t  = r >> 5;      // 0 phi, 1 g, 2 theta
        int oc = r & 31;
        float2 a0 = unpack2(acc[i][0]);
        float2 a1 = unpack2(acc[i][1]);
        float2 a2 = unpack2(acc[i][2]);
        float2 a3 = unpack2(acc[i][3]);
        float* base = (t == 0) ? s_phi : ((t == 1) ? s_g : s_theta);
        float* dst = base + (size_t)b*TOT + ((size_t)oc << 16) + p0 + c0;
        ((float4*)dst)[0] = make_float4(a0.x, a0.y, a1.x, a1.y);
        ((float4*)dst)[1] = make_float4(a2.x, a2.y, a3.x, a3.y);
        if (t == 0) {
            mphi = fmaxf(mphi, fmaxf(fmaxf(a0.x, a0.y), fmaxf(a1.x, a1.y)));
            mphi = fmaxf(mphi, fmaxf(fmaxf(a2.x, a2.y), fmaxf(a3.x, a3.y)));
        } else if (t == 1) {
            mg = fmaxf(mg, fmaxf(fmaxf(a0.x, a0.y), fmaxf(a1.x, a1.y)));
            mg = fmaxf(mg, fmaxf(fmaxf(a2.x, a2.y), fmaxf(a3.x, a3.y)));
        }
    }

    #pragma unroll
    for (int off = 16; off; off >>= 1) {
        mphi = fmaxf(mphi, __shfl_xor_sync(0xffffffffu, mphi, off));
        mg   = fmaxf(mg,   __shfl_xor_sync(0xffffffffu, mg,   off));
    }
    __shared__ float redp[8], redg[8];
    if ((tid & 31) == 0) { redp[tid >> 5] = mphi; redg[tid >> 5] = mg; }
    __syncthreads();
    if (tid == 0) {
        float a = -1e30f, bm = -1e30f;
        #pragma unroll
        for (int i = 0; i < 8; i++) { a = fmaxf(a, redp[i]); bm = fmaxf(bm, redg[i]); }
        atomicMax(&s_maxk[b],     enc_f(a));
        atomicMax(&s_maxk[B + b], enc_f(bm));
    }
}

// ---------------- K2: att_unnorm = exp(g) @ exp(phi)^T  (+ Sphi, Sg) ----------------
// per block: one batch, 512 view-columns; 64x64 partials, atomicAdd into s_att.
__global__ __launch_bounds__(256) void k_att() {
    const int tid = threadIdx.x;
    const int b   = blockIdx.x >> 6;          // 64 blocks per batch
    const int n0  = (blockIdx.x & 63) << 9;
    const float mphi = dec_f(s_maxk[b]);
    const float mg   = dec_f(s_maxk[B + b]);

    __shared__ float eg[32][68];   // [n][c], padded: stores 4-way conflict, loads clean
    __shared__ float ep[32][68];

    const float* gb = s_g   + (size_t)b*TOT;
    const float* pb = s_phi + (size_t)b*TOT;

    ull acc[4][2];
    #pragma unroll
    for (int i = 0; i < 4; i++) { acc[i][0] = 0ull; acc[i][1] = 0ull; }
    float sp = 0.0f, sg = 0.0f;
    const int tr = tid >> 4;   // row group: rows tr*4 .. tr*4+3
    const int tc = tid & 15;   // col group: cols tc*4 .. tc*4+3

    for (int sub = 0; sub < 16; sub++) {
        const int nb = n0 + sub*32;
        __syncthreads();
        for (int i = tid; i < 2048; i += 256) {
            int cc = i >> 5, nn = i & 31;
            float gv = __expf(gb[(size_t)cc*NV + nb + nn] - mg);
            float pv = __expf(pb[(size_t)cc*NV + nb + nn] - mphi);
            eg[nn][cc] = gv; ep[nn][cc] = pv;
            sg += gv; sp += pv;
        }
        __syncthreads();
        #pragma unroll 4
        for (int n = 0; n < 32; n++) {
            ulonglong2 pv = *(const ulonglong2*)&ep[n][tc*4];
            #pragma unroll
            for (int i = 0; i < 4; i++) {
                ull g2 = pack2(eg[n][tr*4 + i]);
                acc[i][0] = fma2(g2, pv.x, acc[i][0]);
                acc[i][1] = fma2(g2, pv.y, acc[i][1]);
            }
        }
    }

    float* attb = s_att + b*4096;
    #pragma unroll
    for (int i = 0; i < 4; i++) {
        int r = tr*4 + i;
        float2 v0 = unpack2(acc[i][0]);
        float2 v1 = unpack2(acc[i][1]);
        atomicAdd(&attb[r*64 + tc*4 + 0], v0.x);
        atomicAdd(&attb[r*64 + tc*4 + 1], v0.y);
        atomicAdd(&attb[r*64 + tc*4 + 2], v1.x);
        atomicAdd(&attb[r*64 + tc*4 + 3], v1.y);
    }

    #pragma unroll
    for (int off = 16; off; off >>= 1) {
        sp += __shfl_xor_sync(0xffffffffu, sp, off);
        sg += __shfl_xor_sync(0xffffffffu, sg, off);
    }
    __shared__ float rsp[8], rsg[8];
    if ((tid & 31) == 0) { rsp[tid >> 5] = sp; rsg[tid >> 5] = sg; }
    __syncthreads();
    if (tid == 0) {
        float a = 0.0f, bm = 0.0f;
        #pragma unroll
        for (int i = 0; i < 8; i++) { a += rsp[i]; bm += rsg[i]; }
        atomicAdd(&s_sum[b],     a);
        atomicAdd(&s_sum[B + b], bm);
    }
}

// ---------------- K3a: fold mask + normalization into C[b][hi][o][d] ----------------
__global__ void k_cmat(const float* __restrict__ wm) {
    int idx = blockIdx.x * 256 + threadIdx.x;   // B*2*64*64 = 65536
    int d  = idx & 63;
    int o  = (idx >> 6) & 63;
    int hi = (idx >> 12) & 1;
    int b  = idx >> 13;
    float inv = 1.0f / (s_sum[b] * s_sum[B + b]);
    const float* attb = s_att + b*4096;
    float acc = 0.0f;
    #pragma unroll
    for (int i = 0; i < 32; i++)
        acc += wm[o*32 + i] * attb[(2*i + hi)*64 + d];
    s_C[idx] = acc * inv;
}

// ---------------- K3b: Out[b][o][hi*NV + n] = sum_d C[b][hi][o][d] * theta[b][d][n] ----------------
__global__ __launch_bounds__(256) void k_out(float* __restrict__ out) {
    __shared__ float ts[64][64];   // theta tile [d][px]
    __shared__ float cs[64][65];   // C [o][d], padded
    const int tid = threadIdx.x;
    const int pb  = blockIdx.x & 511;          // 512 px-tiles per (b,hi)
    const int bh  = blockIdx.x >> 9;
    const int hi  = bh & 1, b = bh >> 1;
    const int p0  = pb << 6;

    const float* th = s_theta + (size_t)b*TOT;
    for (int i = tid; i < 4096; i += 256) {
        int d = i >> 6, p = i & 63;
        ts[d][p] = th[((size_t)d << 15) + p0 + p];
    }
    const float* Cp = s_C + (size_t)(b*2 + hi)*4096;
    for (int i = tid; i < 4096; i += 256) cs[i >> 6][i & 63] = Cp[i];
    __syncthreads();

    const int rg = tid >> 3;       // 0..31 -> rows rg*2, rg*2+1
    const int pg = tid & 7;        // 0..7  -> px pg*8 .. pg*8+7
    const int r0 = rg * 2;
    const int c0 = pg * 8;

    ull acc[2][4];
    #pragma unroll
    for (int i = 0; i < 2; i++)
        #pragma unroll
        for (int j = 0; j < 4; j++) acc[i][j] = 0ull;

    #pragma unroll 4
    for (int d = 0; d < 64; d++) {
        ulonglong2 xa = *(const ulonglong2*)&ts[d][c0];
        ulonglong2 xc = *(const ulonglong2*)&ts[d][c0 + 4];
        #pragma unroll
        for (int i = 0; i < 2; i++) {
            ull c2 = pack2(cs[r0 + i][d]);
            acc[i][0] = fma2(c2, xa.x, acc[i][0]);
            acc[i][1] = fma2(c2, xa.y, acc[i][1]);
            acc[i][2] = fma2(c2, xc.x, acc[i][2]);
            acc[i][3] = fma2(c2, xc.y, acc[i][3]);
        }
    }

    float* ob = out + ((size_t)b << 22) + (size_t)hi*NV + p0 + c0;
    #pragma unroll
    for (int i = 0; i < 2; i++) {
        float2 a0 = unpack2(acc[i][0]);
        float2 a1 = unpack2(acc[i][1]);
        float2 a2 = unpack2(acc[i][2]);
        float2 a3 = unpack2(acc[i][3]);
        float4* d4 = (float4*)(ob + (size_t)(r0 + i)*HW);
        d4[0] = make_float4(a0.x, a0.y, a1.x, a1.y);
        d4[1] = make_float4(a2.x, a2.y, a3.x, a3.y);
    }
}

// ---------------- launch ----------------
extern "C" void kernel_launch(void* const* d_in, const int* in_sizes, int n_in,
                              void* d_out, int out_size) {
    const float* x  = (const float*)d_in[0];
    const float* wp = (const float*)d_in[1];
    const float* wt = (const float*)d_in[2];
    const float* wg = (const float*)d_in[3];
    const float* wm = (const float*)d_in[4];
    float* out = (float*)d_out;

    k_init<<<128, 256>>>();
    k_conv<<<B * (HW/64), 256>>>(x, wp, wt, wg);
    k_att <<<B * (NV/512), 256>>>();
    k_cmat<<<256, 256>>>(wm);
    k_out <<<B * 2 * (NV/64), 256>>>(out);
}

// round 4
// speedup vs baseline: 2.6843x; 2.6843x over previous
#include <cuda_runtime.h>
#include <cuda_bf16.h>
#include <cstdint>

#define B   8
#define C   64
#define IC  32
#define HW  65536
#define NV  32768
#define TOT (IC*HW)

typedef unsigned long long ull;

// ---------------- scratch ----------------
__device__ float s_phi  [(size_t)B*TOT];
__device__ float s_g    [(size_t)B*TOT];
__device__ float s_theta[(size_t)B*TOT];
__device__ unsigned int s_maxk[2*B];
__device__ float s_att[B*64*64];
__device__ float s_sum[2*B];
__device__ float s_C[B*2*64*64];

// ---------------- scalar helpers ----------------
__device__ __forceinline__ unsigned int enc_f(float f) {
    unsigned int u = __float_as_uint(f);
    return (u & 0x80000000u) ? ~u : (u | 0x80000000u);
}
__device__ __forceinline__ float dec_f(unsigned int k) {
    return (k & 0x80000000u) ? __uint_as_float(k ^ 0x80000000u) : __uint_as_float(~k);
}
__device__ __forceinline__ ull fma2(ull a, ull b, ull c) {
    ull d; asm("fma.rn.f32x2 %0, %1, %2, %3;" : "=l"(d) : "l"(a), "l"(b), "l"(c)); return d;
}
__device__ __forceinline__ ull pack2(float x) {
    ull r; asm("mov.b64 %0, {%1, %1};" : "=l"(r) : "f"(x)); return r;
}
__device__ __forceinline__ float2 unpack2(ull v) {
    float2 f; asm("mov.b64 {%0, %1}, %2;" : "=f"(f.x), "=f"(f.y) : "l"(v)); return f;
}
__device__ __forceinline__ uint32_t smem_u32(const void* p) {
    uint32_t a;
    asm("{ .reg .u64 t; cvta.to.shared.u64 t, %1; cvt.u32.u64 %0, t; }" : "=r"(a) : "l"(p));
    return a;
}

// ---------------- warp-MMA helpers (baseline sm_100, no 'a' features) ----------------
__device__ __forceinline__ void ldsm_x4(uint32_t& r0, uint32_t& r1, uint32_t& r2, uint32_t& r3, uint32_t addr) {
    asm volatile("ldmatrix.sync.aligned.m8n8.x4.shared.b16 {%0,%1,%2,%3}, [%4];"
                 : "=r"(r0), "=r"(r1), "=r"(r2), "=r"(r3) : "r"(addr));
}
__device__ __forceinline__ void ldsm_x2(uint32_t& r0, uint32_t& r1, uint32_t addr) {
    asm volatile("ldmatrix.sync.aligned.m8n8.x2.shared.b16 {%0,%1}, [%2];"
                 : "=r"(r0), "=r"(r1) : "r"(addr));
}
__device__ __forceinline__ void mma16816(float* c, uint32_t a0, uint32_t a1, uint32_t a2, uint32_t a3,
                                         uint32_t b0, uint32_t b1) {
    asm volatile("mma.sync.aligned.m16n8k16.row.col.f32.bf16.bf16.f32 "
                 "{%0,%1,%2,%3}, {%4,%5,%6,%7}, {%8,%9}, {%0,%1,%2,%3};"
                 : "+f"(c[0]), "+f"(c[1]), "+f"(c[2]), "+f"(c[3])
                 : "r"(a0), "r"(a1), "r"(a2), "r"(a3), "r"(b0), "r"(b1));
}

// hi/lo bf16 split of a pair of floats -> two packed b32 (bf16x2)
__device__ __forceinline__ void split_pair(float v0, float v1, uint32_t& hpk, uint32_t& lpk) {
    __nv_bfloat16 h0 = __float2bfloat16_rn(v0), h1 = __float2bfloat16_rn(v1);
    hpk = (uint32_t)__bfloat16_as_ushort(h0) | ((uint32_t)__bfloat16_as_ushort(h1) << 16);
    float l0 = v0 - __bfloat162float(h0), l1 = v1 - __bfloat162float(h1);
    __nv_bfloat16 g0 = __float2bfloat16_rn(l0), g1 = __float2bfloat16_rn(l1);
    lpk = (uint32_t)__bfloat16_as_ushort(g0) | ((uint32_t)__bfloat16_as_ushort(g1) << 16);
}

#define PITCH 72           // bf16 elements per smem row (144 B; ldmatrix conflict-free)
#define PITCHB 144

// ---------------- K0: reset accumulators ----------------
__global__ void k_init() {
    int i = blockIdx.x * 256 + threadIdx.x;
    if (i < B*4096) s_att[i] = 0.0f;
    if (i < 2*B) { s_sum[i] = 0.0f; s_maxk[i] = 0u; }
}

// ---------------- K1: conv via mma.sync, bf16 3-split ----------------
// Block: M=128 px, N=96 (phi 0-31 | g 32-63 | theta 64-95), K=64 cin. 256 thr / 8 warps.
// smem: AH[128][72] AL[128][72] WH[96][72] WL[96][72] bf16
__global__ __launch_bounds__(256) void k_conv(const float* __restrict__ x,
                                              const float* __restrict__ wp,
                                              const float* __restrict__ wt,
                                              const float* __restrict__ wg) {
    extern __shared__ char dsm[];
    char* AH = dsm;
    char* AL = dsm + 128*PITCHB;
    char* WH = dsm + 2*128*PITCHB;
    char* WL = dsm + 2*128*PITCHB + 96*PITCHB;
    __shared__ float redp[8], redg[8];

    const int tid  = threadIdx.x;
    const int lane = tid & 31;
    const int wid  = tid >> 5;
    const int b    = blockIdx.x >> 9;
    const int p0   = (blockIdx.x & 511) << 7;

    // weights -> smem (hi/lo): rows 0-31 phi, 32-63 g, 64-95 theta
    for (int i = tid; i < 96*32; i += 256) {
        int row = i >> 5, pr = i & 31;
        const float* src = (row < 32) ? (wp + row*64)
                          : (row < 64 ? wg + (row-32)*64 : wt + (row-64)*64);
        uint32_t h, l;
        split_pair(src[pr*2], src[pr*2+1], h, l);
        *(uint32_t*)(WH + row*PITCHB + pr*4) = h;
        *(uint32_t*)(WL + row*PITCHB + pr*4) = l;
    }
    // x tile -> smem A [px][cin] (hi/lo). 2 threads per px, 16 cin-pairs each.
    {
        const int px = tid & 127;
        const int j0 = (tid >> 7) * 16;
        const float* xb = x + ((size_t)b << 22) + p0 + px;
        #pragma unroll
        for (int j = j0; j < j0 + 16; j++) {
            float v0 = xb[(size_t)(2*j)   << 16];
            float v1 = xb[(size_t)(2*j+1) << 16];
            uint32_t h, l;
            split_pair(v0, v1, h, l);
            *(uint32_t*)(AH + px*PITCHB + j*4) = h;
            *(uint32_t*)(AL + px*PITCHB + j*4) = l;
        }
    }
    __syncthreads();

    const int m0 = wid * 16;
    float c[12][4];
    #pragma unroll
    for (int nt = 0; nt < 12; nt++)
        #pragma unroll
        for (int q = 0; q < 4; q++) c[nt][q] = 0.0f;

    const uint32_t arow = (uint32_t)(m0 + (lane & 15)) * PITCHB + (uint32_t)(lane >> 4) * 16;
    const int bi = lane & 15;
    const uint32_t brow = (uint32_t)(bi & 7) * PITCHB + (uint32_t)(bi >> 3) * 16;

    const char* Asel[3] = { AH, AH, AL };
    const char* Bsel[3] = { WH, WL, WH };
    #pragma unroll
    for (int s = 0; s < 3; s++) {
        const uint32_t abase = smem_u32(Asel[s]);
        const uint32_t bbase = smem_u32(Bsel[s]);
        #pragma unroll
        for (int kk = 0; kk < 4; kk++) {
            uint32_t a0, a1, a2, a3;
            ldsm_x4(a0, a1, a2, a3, abase + arow + kk*32);
            #pragma unroll
            for (int nt = 0; nt < 12; nt++) {
                uint32_t b0, b1;
                ldsm_x2(b0, b1, bbase + brow + (uint32_t)nt*8*PITCHB + kk*32);
                mma16816(c[nt], a0, a1, a2, a3, b0, b1);
            }
        }
    }

    // epilogue: write fragments + phi/g max
    const int qr = lane >> 2;     // 0..7
    const int qc = lane & 3;      // 0..3
    float mphi = -1e30f, mg = -1e30f;
    #pragma unroll
    for (int nt = 0; nt < 12; nt++) {
        int oc = nt*8 + qc*2;
        int t  = oc >> 5;
        int ocl = oc & 31;
        float* base = (t == 0) ? s_phi : ((t == 1) ? s_g : s_theta);
        float* d0 = base + (size_t)b*TOT + ((size_t)ocl << 16) + p0 + m0 + qr;
        d0[0] = c[nt][0];
        d0[1 << 16] = c[nt][1];
        d0[8] = c[nt][2];
        d0[(1 << 16) + 8] = c[nt][3];
        if (t == 0) {
            mphi = fmaxf(mphi, fmaxf(fmaxf(c[nt][0], c[nt][1]), fmaxf(c[nt][2], c[nt][3])));
        } else if (t == 1) {
            mg = fmaxf(mg, fmaxf(fmaxf(c[nt][0], c[nt][1]), fmaxf(c[nt][2], c[nt][3])));
        }
    }
    #pragma unroll
    for (int off = 16; off; off >>= 1) {
        mphi = fmaxf(mphi, __shfl_xor_sync(0xffffffffu, mphi, off));
        mg   = fmaxf(mg,   __shfl_xor_sync(0xffffffffu, mg,   off));
    }
    if (lane == 0) { redp[wid] = mphi; redg[wid] = mg; }
    __syncthreads();
    if (tid == 0) {
        float a = -1e30f, cm = -1e30f;
        #pragma unroll
        for (int i = 0; i < 8; i++) { a = fmaxf(a, redp[i]); cm = fmaxf(cm, redg[i]); }
        atomicMax(&s_maxk[b],     enc_f(a));
        atomicMax(&s_maxk[B + b], enc_f(cm));
    }
}

// ---------------- K2: att_unnorm = exp(g) @ exp(phi)^T  (+ Sphi, Sg) ----------------
__global__ __launch_bounds__(256) void k_att() {
    const int tid = threadIdx.x;
    const int b   = blockIdx.x >> 6;
    const int n0  = (blockIdx.x & 63) << 9;
    const float mphi = dec_f(s_maxk[b]);
    const float mg   = dec_f(s_maxk[B + b]);

    __shared__ float eg[32][68];
    __shared__ float ep[32][68];

    const float* gb = s_g   + (size_t)b*TOT;
    const float* pb = s_phi + (size_t)b*TOT;

    ull acc[4][2];
    #pragma unroll
    for (int i = 0; i < 4; i++) { acc[i][0] = 0ull; acc[i][1] = 0ull; }
    float sp = 0.0f, sg = 0.0f;
    const int tr = tid >> 4;
    const int tc = tid & 15;

    for (int sub = 0; sub < 16; sub++) {
        const int nb = n0 + sub*32;
        __syncthreads();
        for (int i = tid; i < 2048; i += 256) {
            int cc = i >> 5, nn = i & 31;
            float gv = __expf(gb[(size_t)cc*NV + nb + nn] - mg);
            float pv = __expf(pb[(size_t)cc*NV + nb + nn] - mphi);
            eg[nn][cc] = gv; ep[nn][cc] = pv;
            sg += gv; sp += pv;
        }
        __syncthreads();
        #pragma unroll 4
        for (int n = 0; n < 32; n++) {
            ulonglong2 pv = *(const ulonglong2*)&ep[n][tc*4];
            #pragma unroll
            for (int i = 0; i < 4; i++) {
                ull g2 = pack2(eg[n][tr*4 + i]);
                acc[i][0] = fma2(g2, pv.x, acc[i][0]);
                acc[i][1] = fma2(g2, pv.y, acc[i][1]);
            }
        }
    }

    float* attb = s_att + b*4096;
    #pragma unroll
    for (int i = 0; i < 4; i++) {
        int r = tr*4 + i;
        float2 v0 = unpack2(acc[i][0]);
        float2 v1 = unpack2(acc[i][1]);
        atomicAdd(&attb[r*64 + tc*4 + 0], v0.x);
        atomicAdd(&attb[r*64 + tc*4 + 1], v0.y);
        atomicAdd(&attb[r*64 + tc*4 + 2], v1.x);
        atomicAdd(&attb[r*64 + tc*4 + 3], v1.y);
    }

    #pragma unroll
    for (int off = 16; off; off >>= 1) {
        sp += __shfl_xor_sync(0xffffffffu, sp, off);
        sg += __shfl_xor_sync(0xffffffffu, sg, off);
    }
    __shared__ float rsp[8], rsg[8];
    if ((tid & 31) == 0) { rsp[tid >> 5] = sp; rsg[tid >> 5] = sg; }
    __syncthreads();
    if (tid == 0) {
        float a = 0.0f, bm = 0.0f;
        #pragma unroll
        for (int i = 0; i < 8; i++) { a += rsp[i]; bm += rsg[i]; }
        atomicAdd(&s_sum[b],     a);
        atomicAdd(&s_sum[B + b], bm);
    }
}

// ---------------- K3a: fold mask + normalization into C[b][hi][o][d] ----------------
__global__ void k_cmat(const float* __restrict__ wm) {
    int idx = blockIdx.x * 256 + threadIdx.x;
    int d  = idx & 63;
    int o  = (idx >> 6) & 63;
    int hi = (idx >> 12) & 1;
    int b  = idx >> 13;
    float inv = 1.0f / (s_sum[b] * s_sum[B + b]);
    const float* attb = s_att + b*4096;
    float acc = 0.0f;
    #pragma unroll
    for (int i = 0; i < 32; i++)
        acc += wm[o*32 + i] * attb[(2*i + hi)*64 + d];
    s_C[idx] = acc * inv;
}

// ---------------- K4: Out = C @ theta via mma.sync, bf16 3-split ----------------
// Block: M=128 view-cols, N=128 (hi0 64 | hi1 64), K=64. 256 thr / 8 warps.
// smem: AH[128][72] AL[128][72] CH[128][72] CL[128][72] bf16
__global__ __launch_bounds__(256) void k_out(float* __restrict__ out) {
    extern __shared__ char dsm[];
    char* AH = dsm;
    char* AL = dsm + 128*PITCHB;
    char* CH = dsm + 2*128*PITCHB;
    char* CL = dsm + 3*128*PITCHB;

    const int tid  = threadIdx.x;
    const int lane = tid & 31;
    const int wid  = tid >> 5;
    const int b    = blockIdx.x >> 8;
    const int n0   = (blockIdx.x & 255) << 7;

    // C matrices (both halves) -> smem B rows [hi*64 + oc][d]
    for (int i = tid; i < 128*32; i += 256) {
        int row = i >> 5, pr = i & 31;
        int hi = row >> 6, oc = row & 63;
        const float* Cp = s_C + (size_t)(b*2 + hi)*4096 + oc*64 + pr*2;
        uint32_t h, l;
        split_pair(Cp[0], Cp[1], h, l);
        *(uint32_t*)(CH + row*PITCHB + pr*4) = h;
        *(uint32_t*)(CL + row*PITCHB + pr*4) = l;
    }
    // theta view A[n][d]: raw[j][ (d&1)*NV + n ], d=2j,2j+1
    {
        const int px = tid & 127;
        const int j0 = (tid >> 7) * 16;
        const float* th = s_theta + (size_t)b*TOT + n0 + px;
        #pragma unroll
        for (int j = j0; j < j0 + 16; j++) {
            float v0 = th[(size_t)j << 16];
            float v1 = th[((size_t)j << 16) + NV];
            uint32_t h, l;
            split_pair(v0, v1, h, l);
            *(uint32_t*)(AH + px*PITCHB + j*4) = h;
            *(uint32_t*)(AL + px*PITCHB + j*4) = l;
        }
    }
    __syncthreads();

    const int m0 = wid * 16;
    float c[16][4];
    #pragma unroll
    for (int nt = 0; nt < 16; nt++)
        #pragma unroll
        for (int q = 0; q < 4; q++) c[nt][q] = 0.0f;

    const uint32_t arow = (uint32_t)(m0 + (lane & 15)) * PITCHB + (uint32_t)(lane >> 4) * 16;
    const int bi = lane & 15;
    const uint32_t brow = (uint32_t)(bi & 7) * PITCHB + (uint32_t)(bi >> 3) * 16;

    const char* Asel[3] = { AH, AH, AL };
    const char* Bsel[3] = { CH, CL, CH };
    #pragma unroll
    for (int s = 0; s < 3; s++) {
        const uint32_t abase = smem_u32(Asel[s]);
        const uint32_t bbase = smem_u32(Bsel[s]);
        #pragma unroll
        for (int kk = 0; kk < 4; kk++) {
            uint32_t a0, a1, a2, a3;
            ldsm_x4(a0, a1, a2, a3, abase + arow + kk*32);
            #pragma unroll
            for (int nt = 0; nt < 16; nt++) {
                uint32_t b0, b1;
                ldsm_x2(b0, b1, bbase + brow + (uint32_t)nt*8*PITCHB + kk*32);
                mma16816(c[nt], a0, a1, a2, a3, b0, b1);
            }
        }
    }

    // epilogue: out[b][oc][hi*NV + n]
    const int qr = lane >> 2;
    const int qc = lane & 3;
    #pragma unroll
    for (int nt = 0; nt < 16; nt++) {
        int hi = nt >> 3;
        int oc = (nt & 7)*8 + qc*2;
        float* d0 = out + ((size_t)b << 22) + ((size_t)oc << 16) + (size_t)hi*NV + n0 + m0 + qr;
        d0[0] = c[nt][0];
        d0[1 << 16] = c[nt][1];
        d0[8] = c[nt][2];
        d0[(1 << 16) + 8] = c[nt][3];
    }
}

// ---------------- launch ----------------
extern "C" void kernel_launch(void* const* d_in, const int* in_sizes, int n_in,
                              void* d_out, int out_size) {
    const float* x  = (const float*)d_in[0];
    const float* wp = (const float*)d_in[1];
    const float* wt = (const float*)d_in[2];
    const float* wg = (const float*)d_in[3];
    const float* wm = (const float*)d_in[4];
    float* out = (float*)d_out;

    static bool attr_done = false;
    if (!attr_done) {
        cudaFuncSetAttribute(k_conv, cudaFuncAttributeMaxDynamicSharedMemorySize, (2*128 + 2*96)*PITCHB);
        cudaFuncSetAttribute(k_out,  cudaFuncAttributeMaxDynamicSharedMemorySize, 4*128*PITCHB);
        attr_done = true;
    }

    k_init<<<128, 256>>>();
    k_conv<<<B * (HW/128), 256, (2*128 + 2*96)*PITCHB>>>(x, wp, wt, wg);
    k_att <<<B * (NV/512), 256>>>();
    k_cmat<<<256, 256>>>(wm);
    k_out <<<B * (NV/128), 256, 4*128*PITCHB>>>(out);
}

// round 5
// speedup vs baseline: 3.5040x; 1.3054x over previous
#include <cuda_runtime.h>
#include <cuda_bf16.h>
#include <cstdint>

#define B   8
#define C   64
#define IC  32
#define HW  65536
#define NV  32768
#define TOT (IC*HW)

// ---------------- scratch ----------------
__device__ float s_theta[(size_t)B*TOT];
__device__ float s_att[B*64*64];
__device__ float s_sum[2*B];               // [0..7]=Sphi, [8..15]=Sg
__device__ float s_C[B*2*64*64];

// ---------------- helpers ----------------
__device__ __forceinline__ uint32_t smem_u32(const void* p) {
    uint32_t a;
    asm("{ .reg .u64 t; cvta.to.shared.u64 t, %1; cvt.u32.u64 %0, t; }" : "=r"(a) : "l"(p));
    return a;
}
__device__ __forceinline__ void ldsm_x4(uint32_t& r0, uint32_t& r1, uint32_t& r2, uint32_t& r3, uint32_t addr) {
    asm volatile("ldmatrix.sync.aligned.m8n8.x4.shared.b16 {%0,%1,%2,%3}, [%4];"
                 : "=r"(r0), "=r"(r1), "=r"(r2), "=r"(r3) : "r"(addr));
}
__device__ __forceinline__ void mma16816(float* c, uint32_t a0, uint32_t a1, uint32_t a2, uint32_t a3,
                                         uint32_t b0, uint32_t b1) {
    asm volatile("mma.sync.aligned.m16n8k16.row.col.f32.bf16.bf16.f32 "
                 "{%0,%1,%2,%3}, {%4,%5,%6,%7}, {%8,%9}, {%0,%1,%2,%3};"
                 : "+f"(c[0]), "+f"(c[1]), "+f"(c[2]), "+f"(c[3])
                 : "r"(a0), "r"(a1), "r"(a2), "r"(a3), "r"(b0), "r"(b1));
}
__device__ __forceinline__ void split_pair(float v0, float v1, uint32_t& hpk, uint32_t& lpk) {
    __nv_bfloat16 h0 = __float2bfloat16_rn(v0), h1 = __float2bfloat16_rn(v1);
    hpk = (uint32_t)__bfloat16_as_ushort(h0) | ((uint32_t)__bfloat16_as_ushort(h1) << 16);
    float l0 = v0 - __bfloat162float(h0), l1 = v1 - __bfloat162float(h1);
    __nv_bfloat16 g0 = __float2bfloat16_rn(l0), g1 = __float2bfloat16_rn(l1);
    lpk = (uint32_t)__bfloat16_as_ushort(g0) | ((uint32_t)__bfloat16_as_ushort(g1) << 16);
}

#define PITCH  72
#define PITCHB 144

// smem offsets for k_fused (bytes)
#define OFF_AH 0
#define OFF_AL (128*PITCHB)
#define OFF_WH (2*128*PITCHB)
#define OFF_WL (2*128*PITCHB + 96*PITCHB)
#define OFF_EG (2*128*PITCHB + 2*96*PITCHB)
#define OFF_EP (OFF_EG + 64*PITCHB)
#define SMEM_FUSED (OFF_EP + 64*PITCHB)     // 82944 B

// ---------------- K0: reset accumulators ----------------
__global__ void k_init() {
    int i = blockIdx.x * 256 + threadIdx.x;
    if (i < B*4096) s_att[i] = 0.0f;
    if (i < 2*B) s_sum[i] = 0.0f;
}

// ---------------- K1: fused conv + exp + att-partial + theta store ----------------
// Block: batch b, 256 view cols (4 sub-tiles of 64). Per sub-tile:
//   px tile = {n..n+63} half0  ∪  {n..n+63} half1  (M=128)
//   conv mma: N=96 (phi|g|theta), K=64, bf16 3-split
//   theta -> gmem; exp(phi)->EP, exp(g)->EG (bf16); att += EG @ EP^T (single bf16)
__global__ __launch_bounds__(256) void k_fused(const float* __restrict__ x,
                                               const float* __restrict__ wp,
                                               const float* __restrict__ wt,
                                               const float* __restrict__ wg) {
    extern __shared__ char dsm[];
    char* AH = dsm + OFF_AH;
    char* AL = dsm + OFF_AL;
    char* WH = dsm + OFF_WH;
    char* WL = dsm + OFF_WL;
    char* EG = dsm + OFF_EG;
    char* EP = dsm + OFF_EP;
    __shared__ float rsp[8], rsg[8];

    const int tid  = threadIdx.x;
    const int lane = tid & 31;
    const int wid  = tid >> 5;
    const int b    = blockIdx.x >> 7;
    const int v0   = (blockIdx.x & 127) << 8;

    // weights -> smem hi/lo: rows 0-31 phi, 32-63 g, 64-95 theta
    for (int i = tid; i < 96*32; i += 256) {
        int row = i >> 5, pr = i & 31;
        const float* src = (row < 32) ? (wp + row*64)
                          : (row < 64 ? wg + (row-32)*64 : wt + (row-64)*64);
        uint32_t h, l;
        split_pair(src[pr*2], src[pr*2+1], h, l);
        *(uint32_t*)(WH + row*PITCHB + pr*4) = h;
        *(uint32_t*)(WL + row*PITCHB + pr*4) = l;
    }

    // persistent per-warp att accumulators: m-tile mt rows, 4 n-tiles
    const int mt = wid & 3;
    const int ng = wid >> 2;
    float attc[4][4];
    #pragma unroll
    for (int j = 0; j < 4; j++)
        #pragma unroll
        for (int q = 0; q < 4; q++) attc[j][q] = 0.0f;
    float sp = 0.0f, sg = 0.0f;

    // fragment address offsets
    const uint32_t arow  = (uint32_t)(wid*16 + (lane & 15)) * PITCHB + (uint32_t)(lane >> 4) * 16;
    const uint32_t boff  = (uint32_t)((lane >> 4)*8 + (lane & 7)) * PITCHB + (uint32_t)((lane >> 3) & 1) * 16;
    const uint32_t arow2 = (uint32_t)(mt*16 + (lane & 15)) * PITCHB + (uint32_t)(lane >> 4) * 16;
    const int qr = lane >> 2;
    const int qc = lane & 3;

    const uint32_t ahb = smem_u32(AH), alb = smem_u32(AL);
    const uint32_t whb = smem_u32(WH), wlb = smem_u32(WL);
    const uint32_t egb = smem_u32(EG), epb = smem_u32(EP);
    __syncthreads();

    for (int it = 0; it < 4; it++) {
        const int n0it = v0 + it*64;
        // ---- stage x tile: px 0-63 = half0, 64-127 = half1 ----
        {
            const int px = tid & 127;
            const int hi = px >> 6;
            const int j0 = (tid >> 7) * 16;
            const float* xb = x + ((size_t)b << 22) + (size_t)hi*NV + n0it + (px & 63);
            #pragma unroll
            for (int j = j0; j < j0 + 16; j++) {
                float v0f = xb[(size_t)(2*j)   << 16];
                float v1f = xb[(size_t)(2*j+1) << 16];
                uint32_t h, l;
                split_pair(v0f, v1f, h, l);
                *(uint32_t*)(AH + px*PITCHB + j*4) = h;
                *(uint32_t*)(AL + px*PITCHB + j*4) = l;
            }
        }
        __syncthreads();

        // ---- conv mma: 3-split, 12 n-tiles via 6 x4 B loads ----
        float c[12][4];
        #pragma unroll
        for (int nt = 0; nt < 12; nt++)
            #pragma unroll
            for (int q = 0; q < 4; q++) c[nt][q] = 0.0f;

        const uint32_t As[3] = { ahb, ahb, alb };
        const uint32_t Bs[3] = { whb, wlb, whb };
        #pragma unroll
        for (int s = 0; s < 3; s++) {
            #pragma unroll
            for (int kk = 0; kk < 4; kk++) {
                uint32_t a0, a1, a2, a3;
                ldsm_x4(a0, a1, a2, a3, As[s] + arow + kk*32);
                #pragma unroll
                for (int pp = 0; pp < 6; pp++) {
                    uint32_t b0, b1, b2, b3;
                    ldsm_x4(b0, b1, b2, b3, Bs[s] + boff + (uint32_t)pp*16*PITCHB + kk*32);
                    mma16816(c[2*pp],   a0, a1, a2, a3, b0, b1);
                    mma16816(c[2*pp+1], a0, a1, a2, a3, b2, b3);
                }
            }
        }

        // ---- epilogue: theta -> gmem, exp(phi/g) -> smem bf16 ----
        const int r1 = wid*16 + qr;          // px row
        const int hi1 = r1 >> 6;
        const int nl1 = r1 & 63;
        #pragma unroll
        for (int nt = 0; nt < 12; nt++) {
            const int oc = nt*8 + qc*2;
            const int t  = oc >> 5;
            const int ocl = oc & 31;
            if (t == 2) {
                float* d0 = s_theta + (size_t)b*TOT + ((size_t)ocl << 16)
                          + (size_t)hi1*NV + n0it + nl1;
                d0[0] = c[nt][0];
                d0[1 << 16] = c[nt][1];
                d0[8] = c[nt][2];
                d0[(1 << 16) + 8] = c[nt][3];
            } else {
                char* base = (t == 1) ? EG : EP;   // g -> rows of A, phi -> rows of B
                float e0 = __expf(c[nt][0]);
                float e1 = __expf(c[nt][1]);
                float e2 = __expf(c[nt][2]);
                float e3 = __expf(c[nt][3]);
                *(__nv_bfloat16*)(base + (2*ocl + hi1)*PITCHB + nl1*2)       = __float2bfloat16_rn(e0);
                *(__nv_bfloat16*)(base + (2*ocl + 2 + hi1)*PITCHB + nl1*2)   = __float2bfloat16_rn(e1);
                *(__nv_bfloat16*)(base + (2*ocl + hi1)*PITCHB + (nl1+8)*2)     = __float2bfloat16_rn(e2);
                *(__nv_bfloat16*)(base + (2*ocl + 2 + hi1)*PITCHB + (nl1+8)*2) = __float2bfloat16_rn(e3);
                float s4 = (e0 + e1) + (e2 + e3);
                if (t == 0) sp += s4; else sg += s4;
            }
        }
        __syncthreads();

        // ---- att mma: attc += EG(m) @ EP(n)^T over k=64 local cols ----
        #pragma unroll
        for (int kk = 0; kk < 4; kk++) {
            uint32_t a0, a1, a2, a3;
            ldsm_x4(a0, a1, a2, a3, egb + arow2 + kk*32);
            #pragma unroll
            for (int p = 0; p < 2; p++) {
                uint32_t b0, b1, b2, b3;
                ldsm_x4(b0, b1, b2, b3, epb + boff + (uint32_t)(ng*4 + 2*p)*8*PITCHB + kk*32);
                mma16816(attc[2*p],   a0, a1, a2, a3, b0, b1);
                mma16816(attc[2*p+1], a0, a1, a2, a3, b2, b3);
            }
        }
        __syncthreads();
    }

    // ---- flush att partials ----
    float* attb = s_att + b*4096;
    #pragma unroll
    for (int j = 0; j < 4; j++) {
        const int col = (ng*4 + j)*8 + qc*2;
        const int row = mt*16 + qr;
        atomicAdd(&attb[row*64 + col],          attc[j][0]);
        atomicAdd(&attb[row*64 + col + 1],      attc[j][1]);
        atomicAdd(&attb[(row + 8)*64 + col],    attc[j][2]);
        atomicAdd(&attb[(row + 8)*64 + col + 1],attc[j][3]);
    }

    // ---- flush sums ----
    #pragma unroll
    for (int off = 16; off; off >>= 1) {
        sp += __shfl_xor_sync(0xffffffffu, sp, off);
        sg += __shfl_xor_sync(0xffffffffu, sg, off);
    }
    if (lane == 0) { rsp[wid] = sp; rsg[wid] = sg; }
    __syncthreads();
    if (tid == 0) {
        float a = 0.0f, bm = 0.0f;
        #pragma unroll
        for (int i = 0; i < 8; i++) { a += rsp[i]; bm += rsg[i]; }
        atomicAdd(&s_sum[b],     a);
        atomicAdd(&s_sum[B + b], bm);
    }
}

// ---------------- K2: fold mask + normalization into C[b][hi][o][d] ----------------
__global__ void k_cmat(const float* __restrict__ wm) {
    int idx = blockIdx.x * 256 + threadIdx.x;
    int d  = idx & 63;
    int o  = (idx >> 6) & 63;
    int hi = (idx >> 12) & 1;
    int b  = idx >> 13;
    float inv = 1.0f / (s_sum[b] * s_sum[B + b]);
    const float* attb = s_att + b*4096;
    float acc = 0.0f;
    #pragma unroll
    for (int i = 0; i < 32; i++)
        acc += wm[o*32 + i] * attb[(2*i + hi)*64 + d];
    s_C[idx] = acc * inv;
}

// ---------------- K3: Out = C @ theta via mma.sync, bf16 3-split ----------------
__global__ __launch_bounds__(256) void k_out(float* __restrict__ out) {
    extern __shared__ char dsm[];
    char* AH = dsm;
    char* AL = dsm + 128*PITCHB;
    char* CH = dsm + 2*128*PITCHB;
    char* CL = dsm + 3*128*PITCHB;

    const int tid  = threadIdx.x;
    const int lane = tid & 31;
    const int wid  = tid >> 5;
    const int b    = blockIdx.x >> 8;
    const int n0   = (blockIdx.x & 255) << 7;

    for (int i = tid; i < 128*32; i += 256) {
        int row = i >> 5, pr = i & 31;
        int hi = row >> 6, oc = row & 63;
        const float* Cp = s_C + (size_t)(b*2 + hi)*4096 + oc*64 + pr*2;
        uint32_t h, l;
        split_pair(Cp[0], Cp[1], h, l);
        *(uint32_t*)(CH + row*PITCHB + pr*4) = h;
        *(uint32_t*)(CL + row*PITCHB + pr*4) = l;
    }
    {
        const int px = tid & 127;
        const int j0 = (tid >> 7) * 16;
        const float* th = s_theta + (size_t)b*TOT + n0 + px;
        #pragma unroll
        for (int j = j0; j < j0 + 16; j++) {
            float v0 = th[(size_t)j << 16];
            float v1 = th[((size_t)j << 16) + NV];
            uint32_t h, l;
            split_pair(v0, v1, h, l);
            *(uint32_t*)(AH + px*PITCHB + j*4) = h;
            *(uint32_t*)(AL + px*PITCHB + j*4) = l;
        }
    }
    __syncthreads();

    const int m0 = wid * 16;
    float c[16][4];
    #pragma unroll
    for (int nt = 0; nt < 16; nt++)
        #pragma unroll
        for (int q = 0; q < 4; q++) c[nt][q] = 0.0f;

    const uint32_t arow = (uint32_t)(m0 + (lane & 15)) * PITCHB + (uint32_t)(lane >> 4) * 16;
    const uint32_t boff = (uint32_t)((lane >> 4)*8 + (lane & 7)) * PITCHB + (uint32_t)((lane >> 3) & 1) * 16;

    const uint32_t As[3] = { smem_u32(AH), smem_u32(AH), smem_u32(AL) };
    const uint32_t Bs[3] = { smem_u32(CH), smem_u32(CL), smem_u32(CH) };
    #pragma unroll
    for (int s = 0; s < 3; s++) {
        #pragma unroll
        for (int kk = 0; kk < 4; kk++) {
            uint32_t a0, a1, a2, a3;
            ldsm_x4(a0, a1, a2, a3, As[s] + arow + kk*32);
            #pragma unroll
            for (int pp = 0; pp < 8; pp++) {
                uint32_t b0, b1, b2, b3;
                ldsm_x4(b0, b1, b2, b3, Bs[s] + boff + (uint32_t)pp*16*PITCHB + kk*32);
                mma16816(c[2*pp],   a0, a1, a2, a3, b0, b1);
                mma16816(c[2*pp+1], a0, a1, a2, a3, b2, b3);
            }
        }
    }

    const int qr = lane >> 2;
    const int qc = lane & 3;
    #pragma unroll
    for (int nt = 0; nt < 16; nt++) {
        int hi = nt >> 3;
        int oc = (nt & 7)*8 + qc*2;
        float* d0 = out + ((size_t)b << 22) + ((size_t)oc << 16) + (size_t)hi*NV + n0 + m0 + qr;
        d0[0] = c[nt][0];
        d0[1 << 16] = c[nt][1];
        d0[8] = c[nt][2];
        d0[(1 << 16) + 8] = c[nt][3];
    }
}

// ---------------- launch ----------------
extern "C" void kernel_launch(void* const* d_in, const int* in_sizes, int n_in,
                              void* d_out, int out_size) {
    const float* x  = (const float*)d_in[0];
    const float* wp = (const float*)d_in[1];
    const float* wt = (const float*)d_in[2];
    const float* wg = (const float*)d_in[3];
    const float* wm = (const float*)d_in[4];
    float* out = (float*)d_out;

    static bool attr_done = false;
    if (!attr_done) {
        cudaFuncSetAttribute(k_fused, cudaFuncAttributeMaxDynamicSharedMemorySize, SMEM_FUSED);
        cudaFuncSetAttribute(k_out,   cudaFuncAttributeMaxDynamicSharedMemorySize, 4*128*PITCHB);
        attr_done = true;
    }

    k_init <<<128, 256>>>();
    k_fused<<<B * (NV/256), 256, SMEM_FUSED>>>(x, wp, wt, wg);
    k_cmat <<<256, 256>>>(wm);
    k_out  <<<B * (NV/128), 256, 4*128*PITCHB>>>(out);
}